// round 3
// baseline (speedup 1.0000x reference)
#include <cuda_runtime.h>

// WindowWarp R3: stage the (contiguous, monotone) source row-range in shared
// memory via coalesced streaming loads; gather taps from smem.
// B=256, T=2048, C=64, WARP_SIZE=205, L_MAX=2253.

#define TT 2048
#define CC 64
#define TCHUNK 64            // t rows per block
#define MAXROWS 164          // >= 148 worst-case span + margin
#define ROWF4 (CC / 4)

__device__ __forceinline__ float s_of_j(float j, float start, float nl,
                                        float wend, float r204) {
    float s = j;
    if (j >= start) s = fmaf(j - start, r204, start);
    if (j >= wend)  s = j - nl + 205.0f;
    return fminf(fmaxf(s, 0.0f), 2047.0f);
}

__global__ void __launch_bounds__(256) window_warp_kernel(
    const float* __restrict__ x,
    const float* __restrict__ warp_scales,
    const int*   __restrict__ window_starts,
    float* __restrict__ out)
{
    __shared__ float4 sm[MAXROWS * ROWF4];

    int b   = blockIdx.y;
    int t0  = blockIdx.x * TCHUNK;
    int tid = threadIdx.x;
    int lane = tid & 15;       // float4 lane within a row
    int y    = tid >> 4;       // 0..15

    float scale = __ldg(warp_scales + b);
    float start = (float)__ldg(window_starts + b);
    float nl    = floorf(205.0f * scale);
    float Lm1   = (2048.0f - 205.0f + nl) - 1.0f;
    float wend  = start + nl;
    float r204  = 204.0f / fmaxf(nl - 1.0f, 1.0f);

    // --- source row range for this block (s, u monotone) ---
    float u_lo = fminf((float)t0 * Lm1 / 2047.0f, Lm1);
    float u_hi = fminf((float)(t0 + TCHUNK - 1) * Lm1 / 2047.0f, Lm1);
    float j_lo = floorf(u_lo);
    float j_hi = fminf(floorf(u_hi) + 1.0f, 2252.0f);
    int row_lo = max(0, (int)floorf(s_of_j(j_lo, start, nl, wend, r204)) - 1);
    int row_hi = min(TT - 1, (int)floorf(s_of_j(j_hi, start, nl, wend, r204)) + 2);
    int nrows  = row_hi - row_lo + 1;           // <= 149

    // --- coalesced streaming load of rows [row_lo, row_hi] into smem ---
    const float4* xg = reinterpret_cast<const float4*>(x + (size_t)b * TT * CC)
                       + row_lo * ROWF4;
    int nf4 = nrows * ROWF4;
    for (int i = tid; i < nf4; i += 256)
        sm[i] = __ldg(&xg[i]);
    __syncthreads();

    // --- each thread: 4 t rows; warp writes adjacent rows for coalescing ---
    float4* ob = reinterpret_cast<float4*>(out + (size_t)b * TT * CC) + lane;

#pragma unroll
    for (int r = 0; r < 4; r++) {
        int t = t0 + r * 16 + y;

        float u = fminf((float)t * Lm1 / 2047.0f, Lm1);
        float j0 = floorf(u);
        float fu = u - j0;
        float j1 = fminf(j0 + 1.0f, 2252.0f);

        int   idx[4];
        float w[4];
        float jj[2] = {j0, j1};
#pragma unroll
        for (int q = 0; q < 2; q++) {
            float s = s_of_j(jj[q], start, nl, wend, r204);
            float p0 = floorf(s);
            float fr = s - p0;
            int i0 = (int)p0;
            int i1 = min(i0 + 1, TT - 1);
            // defensive clamp into staged range (never triggers in exact math)
            idx[2*q]   = min(max(i0 - row_lo, 0), nrows - 1);
            idx[2*q+1] = min(max(i1 - row_lo, 0), nrows - 1);
            float wu = q ? fu : (1.0f - fu);
            w[2*q]   = wu * (1.0f - fr);
            w[2*q+1] = wu * fr;
        }

        float4 g0 = sm[idx[0] * ROWF4 + lane];
        float4 g1 = sm[idx[1] * ROWF4 + lane];
        float4 g2 = sm[idx[2] * ROWF4 + lane];
        float4 g3 = sm[idx[3] * ROWF4 + lane];

        float4 res;
        res.x = g0.x * w[0]; res.y = g0.y * w[0];
        res.z = g0.z * w[0]; res.w = g0.w * w[0];
        res.x = fmaf(g1.x, w[1], res.x); res.y = fmaf(g1.y, w[1], res.y);
        res.z = fmaf(g1.z, w[1], res.z); res.w = fmaf(g1.w, w[1], res.w);
        res.x = fmaf(g2.x, w[2], res.x); res.y = fmaf(g2.y, w[2], res.y);
        res.z = fmaf(g2.z, w[2], res.z); res.w = fmaf(g2.w, w[2], res.w);
        res.x = fmaf(g3.x, w[3], res.x); res.y = fmaf(g3.y, w[3], res.y);
        res.z = fmaf(g3.z, w[3], res.z); res.w = fmaf(g3.w, w[3], res.w);

        __stcs(&ob[t * ROWF4], res);
    }
}

extern "C" void kernel_launch(void* const* d_in, const int* in_sizes, int n_in,
                              void* d_out, int out_size) {
    const float* x      = (const float*)d_in[0];
    const float* scales = (const float*)d_in[1];
    const int*   starts = (const int*)d_in[2];
    float* out = (float*)d_out;

    dim3 block(256);
    dim3 grid(TT / TCHUNK, 256);   // (32, 256)
    window_warp_kernel<<<grid, block>>>(x, scales, starts, out);
}

// round 4
// speedup vs baseline: 1.2007x; 1.2007x over previous
#include <cuda_runtime.h>

// WindowWarp R4: back to fused direct-gather (R1 winner) with doubled
// instruction efficiency: warp = 8 float4-lanes x 4 t-rows; each thread
// covers 8 channels (two float4 halves) -> 8 front-batched LDG.128,
// same scalar preamble cost amortized over 2x the output.
// B=256, T=2048, C=64, WARP_SIZE=205, L_MAX=2253.

#define BB 256
#define TT 2048
#define CC 64
#define ROWF4 (CC / 4)   // 16 float4 per row

__global__ void __launch_bounds__(256) window_warp_kernel(
    const float* __restrict__ x,
    const float* __restrict__ warp_scales,
    const int*   __restrict__ window_starts,
    float* __restrict__ out)
{
    int b    = blockIdx.y;
    int lane = threadIdx.x;                    // 0..7  (float4 half-row lane)
    int t    = blockIdx.x * 32 + threadIdx.y;  // 0..2047

    float scale = __ldg(warp_scales + b);
    float start = (float)__ldg(window_starts + b);
    float nl    = floorf(205.0f * scale);
    float Lm1   = (2048.0f - 205.0f + nl) - 1.0f;
    float wend  = start + nl;
    float r204  = 204.0f / fmaxf(nl - 1.0f, 1.0f);

    // outer resample position (exact division to match reference rounding)
    float u = (float)t * Lm1 / 2047.0f;
    u = fminf(fmaxf(u, 0.0f), Lm1);
    float j0 = floorf(u);
    float fu = u - j0;
    float j1 = fminf(j0 + 1.0f, 2252.0f);

    // 4 taps: indices + weights
    int   idx[4];
    float w[4];
    float jj[2] = {j0, j1};
#pragma unroll
    for (int q = 0; q < 2; q++) {
        float j = jj[q];
        float s = j;
        if (j >= start) s = fmaf(j - start, r204, start);
        if (j >= wend)  s = j - nl + 205.0f;
        s = fminf(fmaxf(s, 0.0f), 2047.0f);
        float p0 = floorf(s);
        float fr = s - p0;
        int i0 = (int)p0;
        idx[2 * q]     = i0;
        idx[2 * q + 1] = min(i0 + 1, TT - 1);
        float wu = q ? fu : (1.0f - fu);
        w[2 * q]     = wu * (1.0f - fr);
        w[2 * q + 1] = wu * fr;
    }

    const float4* xb = reinterpret_cast<const float4*>(x + (size_t)b * TT * CC);

    // front-batch all 8 independent gathers (4 taps x 2 half-rows)
    float4 g[8];
#pragma unroll
    for (int k = 0; k < 4; k++) {
        g[k]     = __ldg(&xb[idx[k] * ROWF4 + lane]);      // first 128B half
        g[4 + k] = __ldg(&xb[idx[k] * ROWF4 + lane + 8]);  // second 128B half
    }

    float4 rA, rB;
    rA.x = g[0].x * w[0]; rA.y = g[0].y * w[0]; rA.z = g[0].z * w[0]; rA.w = g[0].w * w[0];
    rB.x = g[4].x * w[0]; rB.y = g[4].y * w[0]; rB.z = g[4].z * w[0]; rB.w = g[4].w * w[0];
#pragma unroll
    for (int k = 1; k < 4; k++) {
        rA.x = fmaf(g[k].x, w[k], rA.x);     rA.y = fmaf(g[k].y, w[k], rA.y);
        rA.z = fmaf(g[k].z, w[k], rA.z);     rA.w = fmaf(g[k].w, w[k], rA.w);
        rB.x = fmaf(g[4+k].x, w[k], rB.x);   rB.y = fmaf(g[4+k].y, w[k], rB.y);
        rB.z = fmaf(g[4+k].z, w[k], rB.z);   rB.w = fmaf(g[4+k].w, w[k], rB.w);
    }

    float4* ob = reinterpret_cast<float4*>(out + (size_t)b * TT * CC) + t * ROWF4;
    __stcs(&ob[lane], rA);
    __stcs(&ob[lane + 8], rB);
}

extern "C" void kernel_launch(void* const* d_in, const int* in_sizes, int n_in,
                              void* d_out, int out_size) {
    const float* x      = (const float*)d_in[0];
    const float* scales = (const float*)d_in[1];
    const int*   starts = (const int*)d_in[2];
    float* out = (float*)d_out;

    dim3 block(8, 32);           // 8 float4 lanes x 32 t-rows = 256 threads
    dim3 grid(TT / 32, BB);      // (64, 256)
    window_warp_kernel<<<grid, block>>>(x, scales, starts, out);
}

// round 5
// speedup vs baseline: 1.2071x; 1.0054x over previous
#include <cuda_runtime.h>

// WindowWarp R5: fused direct-gather. Warp = 8 float4-lanes x 4 t-rows;
// each thread covers 8 channels (two float4 halves). 512-thread blocks
// (fewer CTAs, better residency), loads issued as full 256B row pairs in
// ascending row order for clean DRAM bursts.
// B=256, T=2048, C=64, WARP_SIZE=205, L_MAX=2253.

#define BB 256
#define TT 2048
#define CC 64
#define ROWF4 (CC / 4)   // 16 float4 per row

__global__ void __launch_bounds__(512) window_warp_kernel(
    const float* __restrict__ x,
    const float* __restrict__ warp_scales,
    const int*   __restrict__ window_starts,
    float* __restrict__ out)
{
    int b    = blockIdx.y;
    int lane = threadIdx.x;                    // 0..7 (float4 half-row lane)
    int t    = blockIdx.x * 64 + threadIdx.y;  // 0..2047

    float scale = __ldg(warp_scales + b);
    float start = (float)__ldg(window_starts + b);
    float nl    = floorf(205.0f * scale);
    float Lm1   = (2048.0f - 205.0f + nl) - 1.0f;
    float wend  = start + nl;
    float r204  = 204.0f / fmaxf(nl - 1.0f, 1.0f);

    // outer resample position (exact division to match reference rounding)
    float u = fminf((float)t * Lm1 / 2047.0f, Lm1);
    float j0 = floorf(u);
    float fu = u - j0;
    float j1 = fminf(j0 + 1.0f, 2252.0f);

    // 4 taps: indices + weights
    int   idx[4];
    float w[4];
    float jj[2] = {j0, j1};
#pragma unroll
    for (int q = 0; q < 2; q++) {
        float j = jj[q];
        float s = j;
        if (j >= start) s = fmaf(j - start, r204, start);
        if (j >= wend)  s = j - nl + 205.0f;
        s = fminf(fmaxf(s, 0.0f), 2047.0f);
        float p0 = floorf(s);
        float fr = s - p0;
        int i0 = (int)p0;
        idx[2 * q]     = i0;
        idx[2 * q + 1] = min(i0 + 1, TT - 1);
        float wu = q ? fu : (1.0f - fu);
        w[2 * q]     = wu * (1.0f - fr);
        w[2 * q + 1] = wu * fr;
    }

    const float4* xb = reinterpret_cast<const float4*>(x + (size_t)b * TT * CC);

    // front-batch all 8 gathers as full 256B row pairs, ascending row order
    float4 gA[4], gB[4];
#pragma unroll
    for (int k = 0; k < 4; k++) {
        const float4* row = xb + idx[k] * ROWF4;
        gA[k] = __ldg(row + lane);          // bytes [0,128)   of the row
        gB[k] = __ldg(row + lane + 8);      // bytes [128,256) of the row
    }

    float4 rA, rB;
    rA.x = gA[0].x * w[0]; rA.y = gA[0].y * w[0]; rA.z = gA[0].z * w[0]; rA.w = gA[0].w * w[0];
    rB.x = gB[0].x * w[0]; rB.y = gB[0].y * w[0]; rB.z = gB[0].z * w[0]; rB.w = gB[0].w * w[0];
#pragma unroll
    for (int k = 1; k < 4; k++) {
        rA.x = fmaf(gA[k].x, w[k], rA.x); rA.y = fmaf(gA[k].y, w[k], rA.y);
        rA.z = fmaf(gA[k].z, w[k], rA.z); rA.w = fmaf(gA[k].w, w[k], rA.w);
        rB.x = fmaf(gB[k].x, w[k], rB.x); rB.y = fmaf(gB[k].y, w[k], rB.y);
        rB.z = fmaf(gB[k].z, w[k], rB.z); rB.w = fmaf(gB[k].w, w[k], rB.w);
    }

    float4* ob = reinterpret_cast<float4*>(out + (size_t)b * TT * CC) + t * ROWF4;
    __stcs(ob + lane, rA);
    __stcs(ob + lane + 8, rB);
}

extern "C" void kernel_launch(void* const* d_in, const int* in_sizes, int n_in,
                              void* d_out, int out_size) {
    const float* x      = (const float*)d_in[0];
    const float* scales = (const float*)d_in[1];
    const int*   starts = (const int*)d_in[2];
    float* out = (float*)d_out;

    dim3 block(8, 64);           // 512 threads: 8 float4 lanes x 64 t-rows
    dim3 grid(TT / 64, BB);      // (32, 256) = 8192 blocks
    window_warp_kernel<<<grid, block>>>(x, scales, starts, out);
}

// round 6
// speedup vs baseline: 1.2730x; 1.0546x over previous
#include <cuda_runtime.h>

// WindowWarp R6: R4 geometry (warp = 8 float4-lanes x 4 t-rows, each thread
// covers 8 channels) + forced 32-reg budget via __launch_bounds__(256, 8)
// for 100% theoretical occupancy (8 CTAs/SM). Latency-bound gather: resident
// warps = MLP supply.
// B=256, T=2048, C=64, WARP_SIZE=205, L_MAX=2253.

#define BB 256
#define TT 2048
#define CC 64
#define ROWF4 (CC / 4)   // 16 float4 per row

__global__ void __launch_bounds__(256, 8) window_warp_kernel(
    const float* __restrict__ x,
    const float* __restrict__ warp_scales,
    const int*   __restrict__ window_starts,
    float* __restrict__ out)
{
    int b    = blockIdx.y;
    int lane = threadIdx.x;                    // 0..7 (float4 half-row lane)
    int t    = blockIdx.x * 32 + threadIdx.y;  // 0..2047

    float scale = __ldg(warp_scales + b);
    float start = (float)__ldg(window_starts + b);
    float nl    = floorf(205.0f * scale);
    float Lm1   = (2048.0f - 205.0f + nl) - 1.0f;
    float wend  = start + nl;
    float r204  = 204.0f / fmaxf(nl - 1.0f, 1.0f);

    // outer resample position (exact division to match reference rounding)
    float u = fminf((float)t * Lm1 / 2047.0f, Lm1);
    float j0 = floorf(u);
    float fu = u - j0;
    float j1 = fminf(j0 + 1.0f, 2252.0f);

    // 4 taps: indices + weights
    int   idx[4];
    float w[4];
    float jj[2] = {j0, j1};
#pragma unroll
    for (int q = 0; q < 2; q++) {
        float j = jj[q];
        float s = j;
        if (j >= start) s = fmaf(j - start, r204, start);
        if (j >= wend)  s = j - nl + 205.0f;
        s = fminf(fmaxf(s, 0.0f), 2047.0f);
        float p0 = floorf(s);
        float fr = s - p0;
        int i0 = (int)p0;
        idx[2 * q]     = i0;
        idx[2 * q + 1] = min(i0 + 1, TT - 1);
        float wu = q ? fu : (1.0f - fu);
        w[2 * q]     = wu * (1.0f - fr);
        w[2 * q + 1] = wu * fr;
    }

    const float4* xb = reinterpret_cast<const float4*>(x + (size_t)b * TT * CC);

    // front-batch all 8 gathers as full 256B row pairs, ascending row order
    float4 gA[4], gB[4];
#pragma unroll
    for (int k = 0; k < 4; k++) {
        const float4* row = xb + idx[k] * ROWF4;
        gA[k] = __ldg(row + lane);          // bytes [0,128)   of the row
        gB[k] = __ldg(row + lane + 8);      // bytes [128,256) of the row
    }

    float4 rA, rB;
    rA.x = gA[0].x * w[0]; rA.y = gA[0].y * w[0]; rA.z = gA[0].z * w[0]; rA.w = gA[0].w * w[0];
    rB.x = gB[0].x * w[0]; rB.y = gB[0].y * w[0]; rB.z = gB[0].z * w[0]; rB.w = gB[0].w * w[0];
#pragma unroll
    for (int k = 1; k < 4; k++) {
        rA.x = fmaf(gA[k].x, w[k], rA.x); rA.y = fmaf(gA[k].y, w[k], rA.y);
        rA.z = fmaf(gA[k].z, w[k], rA.z); rA.w = fmaf(gA[k].w, w[k], rA.w);
        rB.x = fmaf(gB[k].x, w[k], rB.x); rB.y = fmaf(gB[k].y, w[k], rB.y);
        rB.z = fmaf(gB[k].z, w[k], rB.z); rB.w = fmaf(gB[k].w, w[k], rB.w);
    }

    float4* ob = reinterpret_cast<float4*>(out + (size_t)b * TT * CC) + t * ROWF4;
    __stcs(ob + lane, rA);
    __stcs(ob + lane + 8, rB);
}

extern "C" void kernel_launch(void* const* d_in, const int* in_sizes, int n_in,
                              void* d_out, int out_size) {
    const float* x      = (const float*)d_in[0];
    const float* scales = (const float*)d_in[1];
    const int*   starts = (const int*)d_in[2];
    float* out = (float*)d_out;

    dim3 block(8, 32);           // 256 threads: 8 float4 lanes x 32 t-rows
    dim3 grid(TT / 32, BB);      // (64, 256)
    window_warp_kernel<<<grid, block>>>(x, scales, starts, out);
}